// round 17
// baseline (speedup 1.0000x reference)
#include <cuda_runtime.h>
#include <cuda_bf16.h>
#include <cuda_fp16.h>
#include <cstdint>

// Problem constants
#define BATCH 4
#define SEQ   2048
#define DIM   1024
#define NHEAD 16
#define HDIM  64
#define FFDIM 4096
#define ROWS  (BATCH * SEQ)            // 8192
#define LN_EPS 1e-6f

// ---------------- scratch (device globals; no allocation) ----------------
__device__ float g_x  [(size_t)ROWS * DIM];
__device__ __half g_qkv16[(size_t)ROWS * 3 * DIM];
__device__ __half g_h16 [(size_t)ROWS * DIM];
__device__ __half g_c16 [(size_t)ROWS * DIM];
__device__ __half g_f116[(size_t)ROWS * FFDIM];
__device__ __half g_x16 [(size_t)ROWS * DIM];
// fp16 weights: Wq|Wk|Wv|Wo|WgateUp(interleaved)|Wdown|W_out
#define WOFF_Q  0
#define WOFF_K  1048576
#define WOFF_V  2097152
#define WOFF_O  3145728
#define WOFF_GU 4194304
#define WOFF_D  12582912
#define WOFF_H  16777216
#define WTOT    17825792
__device__ __half g_whi[(size_t)WTOT];
// fp16 attention operands, [B,H,S,HD] layout
__device__ __half g_q16a[(size_t)ROWS * DIM];
__device__ __half g_k16 [(size_t)ROWS * DIM];
__device__ __half g_v16 [(size_t)ROWS * DIM];

__device__ __forceinline__ uint32_t smem_u32(const void* p) {
    uint32_t a;
    asm("{ .reg .u64 t; cvta.to.shared.u64 t, %1; cvt.u32.u64 %0, t; }"
        : "=r"(a) : "l"(p));
    return a;
}
__device__ __forceinline__ void ldmx4(uint32_t addr, uint32_t& r0, uint32_t& r1,
                                      uint32_t& r2, uint32_t& r3) {
    asm volatile("ldmatrix.sync.aligned.m8n8.x4.shared.b16 {%0,%1,%2,%3}, [%4];"
                 : "=r"(r0), "=r"(r1), "=r"(r2), "=r"(r3) : "r"(addr));
}
__device__ __forceinline__ void ldmx4t(uint32_t addr, uint32_t& r0, uint32_t& r1,
                                       uint32_t& r2, uint32_t& r3) {
    asm volatile("ldmatrix.sync.aligned.m8n8.x4.trans.shared.b16 {%0,%1,%2,%3}, [%4];"
                 : "=r"(r0), "=r"(r1), "=r"(r2), "=r"(r3) : "r"(addr));
}
__device__ __forceinline__ void mma16816h(float* c, uint32_t a0, uint32_t a1,
                                          uint32_t a2, uint32_t a3,
                                          uint32_t b0, uint32_t b1) {
    asm volatile(
        "mma.sync.aligned.m16n8k16.row.col.f32.f16.f16.f32 "
        "{%0,%1,%2,%3}, {%4,%5,%6,%7}, {%8,%9}, {%0,%1,%2,%3};"
        : "+f"(c[0]), "+f"(c[1]), "+f"(c[2]), "+f"(c[3])
        : "r"(a0), "r"(a1), "r"(a2), "r"(a3), "r"(b0), "r"(b1));
}
__device__ __forceinline__ float ex2f(float x) {
    float r;
    asm("ex2.approx.f32 %0, %1;" : "=f"(r) : "f"(x));
    return r;
}
#define CPA16(dst, src) \
    asm volatile("cp.async.cg.shared.global [%0], [%1], 16;" :: "r"(dst), "l"(src))
#define CPA_COMMIT() asm volatile("cp.async.commit_group;" ::: "memory")
#define CPA_WAIT(n)  asm volatile("cp.async.wait_group %0;" :: "n"(n) : "memory")

// ---- merged weight convert: all weights in ONE launch (block-segmented) ---
__global__ void wcvt_all(const float* __restrict__ Wq, const float* __restrict__ Wk,
                         const float* __restrict__ Wv, const float* __restrict__ Wo,
                         const float* __restrict__ Wg, const float* __restrict__ Wu,
                         const float* __restrict__ Wd, const float* __restrict__ Wh,
                         __half* __restrict__ whi) {
    int blk = blockIdx.x;
    int tid = threadIdx.x;
    if (blk < 4096) {                       // Q,K,V,O
        int seg = blk >> 10;
        int t = (blk & 1023) * 256 + tid;
        const float* src = (seg == 0) ? Wq : (seg == 1) ? Wk : (seg == 2) ? Wv : Wo;
        __half* dst = whi + (size_t)seg * 1048576;
        float4 v = *(const float4*)(src + (size_t)t * 4);
        __half2 h0 = __floats2half2_rn(v.x, v.y), h1 = __floats2half2_rn(v.z, v.w);
        uint2 o = { *(uint32_t*)&h0, *(uint32_t*)&h1 };
        *(uint2*)(dst + (size_t)t * 4) = o;
    } else if (blk < 8192) {                // gate/up interleaved
        int t = (blk - 4096) * 256 + tid;
        int r = t >> 8, c4 = t & 255;
        float4 vg = *(const float4*)(Wg + (size_t)t * 4);
        float4 vu = *(const float4*)(Wu + (size_t)t * 4);
        __half2 g0 = __floats2half2_rn(vg.x, vg.y), g1 = __floats2half2_rn(vg.z, vg.w);
        __half2 u0 = __floats2half2_rn(vu.x, vu.y), u1 = __floats2half2_rn(vu.z, vu.w);
        uint2 go = { *(uint32_t*)&g0, *(uint32_t*)&g1 };
        uint2 uo = { *(uint32_t*)&u0, *(uint32_t*)&u1 };
        *(uint2*)(whi + WOFF_GU + (size_t)(2 * r) * DIM + c4 * 4)     = go;
        *(uint2*)(whi + WOFF_GU + (size_t)(2 * r + 1) * DIM + c4 * 4) = uo;
    } else if (blk < 12288) {               // Wdown
        int t = (blk - 8192) * 256 + tid;
        float4 v = *(const float4*)(Wd + (size_t)t * 4);
        __half2 h0 = __floats2half2_rn(v.x, v.y), h1 = __floats2half2_rn(v.z, v.w);
        uint2 o = { *(uint32_t*)&h0, *(uint32_t*)&h1 };
        *(uint2*)(whi + WOFF_D + (size_t)t * 4) = o;
    } else {                                // W_out
        int t = (blk - 12288) * 256 + tid;
        float4 v = *(const float4*)(Wh + (size_t)t * 4);
        __half2 h0 = __floats2half2_rn(v.x, v.y), h1 = __floats2half2_rn(v.z, v.w);
        uint2 o = { *(uint32_t*)&h0, *(uint32_t*)&h1 };
        *(uint2*)(whi + WOFF_H + (size_t)t * 4) = o;
    }
}

// ================= gemm_s: single-term fp16 GEMM ===========================
// Tile 128x128, BK=64, 3-stage cp.async (32KB stage), SW64 swizzle,
// single __syncthreads per K-chunk, wait_group 1, 2 CTAs/SM.
#define SBM 128
#define SBN 128
#define SBK 64
#define S_W   16384
#define SSTG  32768
#define SMEM3 (3 * SSTG)       // 98304 -> 2 CTAs/SM

__global__ __launch_bounds__(256, 2)
void gemm_s(const __half* __restrict__ A, const __half* __restrict__ W,
            const float* __restrict__ res, const float* __restrict__ bias,
            float* __restrict__ C, __half* __restrict__ C16,
            __half* __restrict__ GU,
            int M, int N, int K) {
    extern __shared__ char smem[];
    uint32_t sb = smem_u32(smem);
    int tid = threadIdx.x, wid = tid >> 5, lane = tid & 31;
    int bm = blockIdx.y * SBM, bn = blockIdx.x * SBN;
    int warp_m = (wid >> 2) * 64, warp_n = (wid & 3) * 32;

    uint32_t strow = (uint32_t)(tid >> 2);
    uint32_t stc   = (uint32_t)(tid & 3) * 16;
    uint32_t st_off = strow * 64 + (stc ^ (((strow >> 1) & 3u) << 4));
    const __half* Ap = A + (size_t)(bm + strow) * K + (tid & 3) * 8;
    const __half* Wp = W + (size_t)(bn + strow) * K + (tid & 3) * 8;

    auto load_stage = [&](int s, int chunk) {
        uint32_t base = sb + (uint32_t)s * SSTG;
        size_t ko = (size_t)chunk * SBK;
        #pragma unroll
        for (int sub = 0; sub < 2; sub++) {
            #pragma unroll
            for (int j = 0; j < 2; j++) {
                uint32_t d = base + sub * 8192 + st_off + j * 4096;
                size_t ro = (size_t)j * 64 * K + ko + sub * 32;
                CPA16(d,       (const char*)(Ap + ro));
                CPA16(d + S_W, (const char*)(Wp + ro));
            }
        }
    };

    int ra = warp_m + (lane & 15);
    uint32_t a_row = (uint32_t)ra * 64;
    uint32_t swa = (((uint32_t)ra >> 1) & 3u) << 4;
    int rb = warp_n + (lane & 7) + ((lane >> 4) & 1) * 8;
    uint32_t b_row = (uint32_t)rb * 64;
    uint32_t swb = (((uint32_t)rb >> 1) & 3u) << 4;
    uint32_t col_a[2], col_b[2];
    int ha = ((lane >> 4) & 1) * 16;
    int hb = ((lane >> 3) & 1) * 16;
    #pragma unroll
    for (int ks = 0; ks < 2; ks++) {
        col_a[ks] = ((uint32_t)(ks * 32 + ha)) ^ swa;
        col_b[ks] = ((uint32_t)(ks * 32 + hb)) ^ swb;
    }

    float acc[4][4][4];
    #pragma unroll
    for (int i = 0; i < 4; i++)
        #pragma unroll
        for (int j = 0; j < 4; j++)
            #pragma unroll
            for (int r = 0; r < 4; r++) acc[i][j][r] = 0.f;

    const int nk = K / SBK;
    load_stage(0, 0);
    CPA_COMMIT();
    if (nk > 1) { load_stage(1, 1); CPA_COMMIT(); }

    int sc = 0;
    for (int i = 0; i < nk; i++) {
        if (i + 1 < nk) { CPA_WAIT(1); } else { CPA_WAIT(0); }
        __syncthreads();
        if (i + 2 < nk) {
            int snx = sc + 2; if (snx >= 3) snx -= 3;
            load_stage(snx, i + 2);
            CPA_COMMIT();
        }

        uint32_t base = sb + (uint32_t)sc * SSTG;
        #pragma unroll
        for (int ks = 0; ks < 4; ks++) {
            uint32_t soff = (uint32_t)(ks >> 1) * 8192;
            uint32_t ca = col_a[ks & 1], cb = col_b[ks & 1];
            uint32_t bhr[2][4];
            #pragma unroll
            for (int np = 0; np < 2; np++) {
                uint32_t bd = base + S_W + soff + b_row + (uint32_t)np * 1024 + cb;
                ldmx4(bd, bhr[np][0], bhr[np][1], bhr[np][2], bhr[np][3]);
            }
            uint32_t ar[4][4];
            #pragma unroll
            for (int mf = 0; mf < 4; mf++) {
                uint32_t ad = base + soff + a_row + (uint32_t)mf * 1024 + ca;
                ldmx4(ad, ar[mf][0], ar[mf][1], ar[mf][2], ar[mf][3]);
            }
            #pragma unroll
            for (int mf = 0; mf < 4; mf++)
                #pragma unroll
                for (int nf = 0; nf < 4; nf++)
                    mma16816h(acc[mf][nf],
                              ar[mf][0], ar[mf][1], ar[mf][2], ar[mf][3],
                              bhr[nf >> 1][(nf & 1) * 2], bhr[nf >> 1][(nf & 1) * 2 + 1]);
        }
        sc = (sc == 2) ? 0 : sc + 1;
    }

    // ---- epilogue ----
    int tr = lane >> 2, tc = (lane & 3) * 2;
    #pragma unroll
    for (int mf = 0; mf < 4; mf++) {
        #pragma unroll
        for (int nf = 0; nf < 4; nf++) {
            int row0 = bm + warp_m + mf * 16 + tr;
            int col  = bn + warp_n + nf * 8 + tc;
            float* c = acc[mf][nf];
            float v[4] = {c[0], c[1], c[2], c[3]};
            size_t o0 = (size_t)row0 * N + col;
            size_t o1 = (size_t)(row0 + 8) * N + col;
            if (GU) {
                float r0 = v[1] * (v[0] / (1.f + expf(-v[0])));
                float r1 = v[3] * (v[2] / (1.f + expf(-v[2])));
                size_t p0 = (size_t)row0 * (N / 2) + (col >> 1);
                size_t p1 = (size_t)(row0 + 8) * (N / 2) + (col >> 1);
                GU[p0] = __float2half_rn(r0);
                GU[p1] = __float2half_rn(r1);
                continue;
            }
            if (res) {
                float2 r0 = *(const float2*)(res + o0);
                float2 r1 = *(const float2*)(res + o1);
                v[0] += r0.x; v[1] += r0.y; v[2] += r1.x; v[3] += r1.y;
            }
            if (bias) {
                float2 bb = *(const float2*)(bias + col);
                v[0] += bb.x; v[1] += bb.y; v[2] += bb.x; v[3] += bb.y;
            }
            if (C) {
                *(float2*)(C + o0) = {v[0], v[1]};
                *(float2*)(C + o1) = {v[2], v[3]};
            }
            if (C16) {
                __half2 h0 = __floats2half2_rn(v[0], v[1]);
                __half2 h1 = __floats2half2_rn(v[2], v[3]);
                *(__half2*)(C16 + o0) = h0;
                *(__half2*)(C16 + o1) = h1;
            }
        }
    }
}

// ---------------- RMSNorm -> fp16 ----------------
__global__ void rmsnorm_kernel(const float* __restrict__ x,
                               const float* __restrict__ w,
                               __half* __restrict__ o16) {
    int row = blockIdx.x;
    const float* xr = x + (size_t)row * DIM;
    float s = 0.f;
    #pragma unroll
    for (int i = threadIdx.x; i < DIM; i += 256) {
        float v = xr[i];
        s += v * v;
    }
    __shared__ float red[8];
    #pragma unroll
    for (int o = 16; o; o >>= 1) s += __shfl_down_sync(0xffffffffu, s, o);
    if ((threadIdx.x & 31) == 0) red[threadIdx.x >> 5] = s;
    __syncthreads();
    if (threadIdx.x < 8) {
        float t = red[threadIdx.x];
        #pragma unroll
        for (int o = 4; o; o >>= 1) t += __shfl_down_sync(0xffu, t, o);
        if (threadIdx.x == 0) red[0] = t;
    }
    __syncthreads();
    float inv = rsqrtf(red[0] * (1.0f / DIM) + LN_EPS);
    #pragma unroll
    for (int i = threadIdx.x; i < DIM; i += 256) {
        float v = xr[i] * inv * w[i];
        o16[(size_t)row * DIM + i] = __float2half_rn(v);
    }
}

// ------ RoPE + V convert on fp16 qkv [rows,3072] -> fp16 [B,H,S,HD] --------
#define QSCALE 0.18033688011111793f   // 0.125 * log2(e)
__global__ void rope_v_cvt_kernel(const __half* __restrict__ QKV,
                                  __half* __restrict__ q16,
                                  __half* __restrict__ k16,
                                  __half* __restrict__ v16) {
    int idx = blockIdx.x * 256 + threadIdx.x;
    if (idx >= BATCH * SEQ * NHEAD * (HDIM / 2)) return;
    int d = idx & 31;
    int h = (idx >> 5) & (NHEAD - 1);
    int s = (idx >> 9) & (SEQ - 1);
    int b = idx >> 20;
    size_t ibase = ((size_t)b * SEQ + s) * (3 * DIM) + (size_t)h * HDIM;
    size_t obase = (((size_t)b * NHEAD + h) * SEQ + s) * HDIM;
    float inv = expf(-(float)d * (9.210340371976184f / 32.f));
    float ang = (float)s * inv;
    float sn, cs;
    sincosf(ang, &sn, &cs);
    {
        float x1 = __half2float(QKV[ibase + d]);
        float x2 = __half2float(QKV[ibase + d + 32]);
        float r1 = (x1 * cs - x2 * sn) * QSCALE;
        float r2 = (x2 * cs + x1 * sn) * QSCALE;
        q16[obase + d]      = __float2half_rn(r1);
        q16[obase + d + 32] = __float2half_rn(r2);
    }
    {
        float x1 = __half2float(QKV[ibase + DIM + d]);
        float x2 = __half2float(QKV[ibase + DIM + d + 32]);
        float r1 = x1 * cs - x2 * sn;
        float r2 = x2 * cs + x1 * sn;
        k16[obase + d]      = __float2half_rn(r1);
        k16[obase + d + 32] = __float2half_rn(r2);
    }
    {
        v16[obase + d]      = QKV[ibase + 2 * DIM + d];
        v16[obase + d + 32] = QKV[ibase + 2 * DIM + d + 32];
    }
}

// ============ MMA flash attention: 128-query tile, 8 warps =================
// Each warp owns 16 q-rows (identical per-warp math to the 64-q version);
// K/V tiles (64 keys, fp16, 2 stages) shared by all 8 warps -> L2 traffic /2.
#define AROWB 144
#define A_Q   0                   // 128 rows * 144B = 18432
#define A_K0  18432               // 2 stages x 9216
#define A_V0  36864               // 2 stages x 9216
#define ASMEM 55296

__global__ __launch_bounds__(256)
void attn_mma(const __half* __restrict__ q16,
              const __half* __restrict__ k16,
              const __half* __restrict__ v16,
              __half* __restrict__ O16) {
    extern __shared__ char smem[];
    uint32_t sb = smem_u32(smem);
    int tid = threadIdx.x, wid = tid >> 5, lane = tid & 31;
    int b = blockIdx.z, h = blockIdx.y;
    int q0 = blockIdx.x * 128;
    size_t hoff = ((size_t)b * NHEAD + h) * SEQ * HDIM;

    // ---- load 128-row Q tile ----
    {
        const uint4* q4 = (const uint4*)(q16 + hoff + (size_t)q0 * HDIM);
        #pragma unroll
        for (int j = 0; j < 4; j++) {
            int f = tid + j * 256;
            int r = f >> 3, c = f & 7;
            *(uint4*)(smem + A_Q + r * AROWB + c * 16) = q4[r * 8 + c];
        }
    }
    __syncthreads();

    uint32_t qf[4][4];
    {
        uint32_t a_base = sb + (uint32_t)(wid * 16 + (lane & 15)) * AROWB + ((lane >> 4) & 1) * 16;
        #pragma unroll
        for (int ks = 0; ks < 4; ks++)
            ldmx4(a_base + ks * 32, qf[ks][0], qf[ks][1], qf[ks][2], qf[ks][3]);
    }

    float ctx[8][4];
    #pragma unroll
    for (int j = 0; j < 8; j++)
        #pragma unroll
        for (int r = 0; r < 4; r++) ctx[j][r] = 0.f;
    float m0 = -1e30f, m1 = -1e30f, l0 = 0.f, l1 = 0.f;

    const __half* k_g = k16 + hoff;
    const __half* v_g = v16 + hoff;

    // K/V tile loads: 64 rows x 8 chunks = 512 chunks over 256 threads
    {
        #pragma unroll
        for (int j = 0; j < 2; j++) {
            int f = tid + j * 256;
            int r = f >> 3, c = f & 7;
            uint32_t so = (uint32_t)(r * AROWB + c * 16);
            CPA16(sb + A_K0 + so, (const char*)(k_g + r * 64 + c * 8));
            CPA16(sb + A_V0 + so, (const char*)(v_g + r * 64 + c * 8));
        }
        CPA_COMMIT();
    }

    const int NT = SEQ / 64;
    for (int t = 0; t < NT; t++) {
        int s = t & 1;
        if (t + 1 < NT) {
            int nxt = s ^ 1;
            size_t goff = (size_t)(t + 1) * 64 * 64;
            #pragma unroll
            for (int j = 0; j < 2; j++) {
                int f = tid + j * 256;
                int r = f >> 3, c = f & 7;
                uint32_t so = (uint32_t)(r * AROWB + c * 16);
                CPA16(sb + A_K0 + nxt * 9216 + so, (const char*)(k_g + goff + r * 64 + c * 8));
                CPA16(sb + A_V0 + nxt * 9216 + so, (const char*)(v_g + goff + r * 64 + c * 8));
            }
            CPA_COMMIT();
            CPA_WAIT(1);
        } else {
            CPA_WAIT(0);
        }
        __syncthreads();

        uint32_t kbse = sb + A_K0 + s * 9216;
        uint32_t vbse = sb + A_V0 + s * 9216;

        float sc[8][4];
        #pragma unroll
        for (int j = 0; j < 8; j++)
            #pragma unroll
            for (int r = 0; r < 4; r++) sc[j][r] = 0.f;

        uint32_t b_off = (uint32_t)((lane & 7) + ((lane >> 4) & 1) * 8) * AROWB +
                         ((lane >> 3) & 1) * 16;
        #pragma unroll
        for (int ks = 0; ks < 4; ks++) {
            #pragma unroll
            for (int ng = 0; ng < 4; ng++) {
                uint32_t bh0, bh1, bh2, bh3;
                uint32_t ad = b_off + (uint32_t)ng * (16 * AROWB) + ks * 32;
                ldmx4(kbse + ad, bh0, bh1, bh2, bh3);
                mma16816h(sc[2 * ng],     qf[ks][0], qf[ks][1], qf[ks][2], qf[ks][3], bh0, bh1);
                mma16816h(sc[2 * ng + 1], qf[ks][0], qf[ks][1], qf[ks][2], qf[ks][3], bh2, bh3);
            }
        }

        float mn0 = m0, mn1 = m1;
        #pragma unroll
        for (int j = 0; j < 8; j++) {
            mn0 = fmaxf(mn0, fmaxf(sc[j][0], sc[j][1]));
            mn1 = fmaxf(mn1, fmaxf(sc[j][2], sc[j][3]));
        }
        mn0 = fmaxf(mn0, __shfl_xor_sync(0xffffffffu, mn0, 1));
        mn0 = fmaxf(mn0, __shfl_xor_sync(0xffffffffu, mn0, 2));
        mn1 = fmaxf(mn1, __shfl_xor_sync(0xffffffffu, mn1, 1));
        mn1 = fmaxf(mn1, __shfl_xor_sync(0xffffffffu, mn1, 2));
        float corr0 = ex2f(m0 - mn0);
        float corr1 = ex2f(m1 - mn1);
        m0 = mn0; m1 = mn1;
        l0 *= corr0; l1 *= corr1;
        #pragma unroll
        for (int j = 0; j < 8; j++) {
            ctx[j][0] *= corr0; ctx[j][1] *= corr0;
            ctx[j][2] *= corr1; ctx[j][3] *= corr1;
        }
        uint32_t pa[8], pb[8];
        #pragma unroll
        for (int j = 0; j < 8; j++) {
            float p0 = ex2f(sc[j][0] - mn0);
            float p1 = ex2f(sc[j][1] - mn0);
            float p2 = ex2f(sc[j][2] - mn1);
            float p3 = ex2f(sc[j][3] - mn1);
            l0 += p0 + p1; l1 += p2 + p3;
            __half2 t0 = __floats2half2_rn(p0, p1);
            __half2 t1 = __floats2half2_rn(p2, p3);
            pa[j] = *(uint32_t*)&t0;
            pb[j] = *(uint32_t*)&t1;
        }

        uint32_t v_off = (uint32_t)(lane & 15) * AROWB + ((lane >> 4) & 1) * 16;
        #pragma unroll
        for (int ks = 0; ks < 4; ks++) {
            #pragma unroll
            for (int nd = 0; nd < 4; nd++) {
                uint32_t r0, r1, r2, r3;
                ldmx4t(vbse + v_off + (uint32_t)ks * (16 * AROWB) + nd * 32, r0, r1, r2, r3);
                mma16816h(ctx[nd * 2],     pa[2 * ks], pb[2 * ks], pa[2 * ks + 1], pb[2 * ks + 1], r0, r1);
                mma16816h(ctx[nd * 2 + 1], pa[2 * ks], pb[2 * ks], pa[2 * ks + 1], pb[2 * ks + 1], r2, r3);
            }
        }
        __syncthreads();
    }

    l0 += __shfl_xor_sync(0xffffffffu, l0, 1);
    l0 += __shfl_xor_sync(0xffffffffu, l0, 2);
    l1 += __shfl_xor_sync(0xffffffffu, l1, 1);
    l1 += __shfl_xor_sync(0xffffffffu, l1, 2);
    float i0 = 1.f / l0, i1 = 1.f / l1;

    int tr = lane >> 2, tc = (lane & 3) * 2;
    int row0 = q0 + wid * 16 + tr;
    #pragma unroll
    for (int f = 0; f < 8; f++) {
        int d = f * 8 + tc;
        float* c = ctx[f];
        size_t o0 = ((size_t)b * SEQ + row0) * DIM + (size_t)h * HDIM + d;
        size_t o1 = ((size_t)b * SEQ + row0 + 8) * DIM + (size_t)h * HDIM + d;
        __half2 h0 = __floats2half2_rn(c[0] * i0, c[1] * i0);
        __half2 h1 = __floats2half2_rn(c[2] * i1, c[3] * i1);
        *(__half2*)(O16 + o0) = h0;
        *(__half2*)(O16 + o1) = h1;
    }
}

// ---------------- launch ----------------
extern "C" void kernel_launch(void* const* d_in, const int* in_sizes, int n_in,
                              void* d_out, int out_size) {
    const float* x_in   = (const float*)d_in[0];
    const float* Wq     = (const float*)d_in[1];
    const float* Wk     = (const float*)d_in[2];
    const float* Wv     = (const float*)d_in[3];
    const float* Wo     = (const float*)d_in[4];
    const float* ln1_w  = (const float*)d_in[5];
    const float* ln2_w  = (const float*)d_in[6];
    const float* Wgate  = (const float*)d_in[7];
    const float* Wup    = (const float*)d_in[8];
    const float* Wdown  = (const float*)d_in[9];
    const float* W_out  = (const float*)d_in[10];
    const float* b_out  = (const float*)d_in[11];
    float* out = (float*)d_out;

    float *x;
    __half *qkv16, *h16, *c16, *f116, *x16, *whi;
    __half *q16a, *k16, *v16;
    cudaGetSymbolAddress((void**)&x,     g_x);
    cudaGetSymbolAddress((void**)&qkv16, g_qkv16);
    cudaGetSymbolAddress((void**)&h16,   g_h16);
    cudaGetSymbolAddress((void**)&c16,   g_c16);
    cudaGetSymbolAddress((void**)&f116,  g_f116);
    cudaGetSymbolAddress((void**)&x16,   g_x16);
    cudaGetSymbolAddress((void**)&whi,   g_whi);
    cudaGetSymbolAddress((void**)&q16a,  g_q16a);
    cudaGetSymbolAddress((void**)&k16,   g_k16);
    cudaGetSymbolAddress((void**)&v16,   g_v16);

    cudaFuncSetAttribute(gemm_s,   cudaFuncAttributeMaxDynamicSharedMemorySize, SMEM3);
    cudaFuncSetAttribute(attn_mma, cudaFuncAttributeMaxDynamicSharedMemorySize, ASMEM);

    // --- all weight converts in one launch ---
    wcvt_all<<<13312, 256>>>(Wq, Wk, Wv, Wo, Wgate, Wup, Wdown, W_out, whi);

    // --- attention block ---
    rmsnorm_kernel<<<ROWS, 256>>>(x_in, ln1_w, h16);

    dim3 gqkv(3 * DIM / SBN, ROWS / SBM);   // (24, 64)
    gemm_s<<<gqkv, 256, SMEM3>>>(h16, whi + WOFF_Q,
                                 nullptr, nullptr,
                                 nullptr, qkv16, nullptr, ROWS, 3 * DIM, DIM);

    int rope_total = BATCH * SEQ * NHEAD * (HDIM / 2);
    rope_v_cvt_kernel<<<(rope_total + 255) / 256, 256>>>(qkv16, q16a, k16, v16);

    dim3 ga(SEQ / 128, NHEAD, BATCH);   // (16, 16, 4) = 1024 CTAs
    attn_mma<<<ga, 256, ASMEM>>>(q16a, k16, v16, c16);

    dim3 g1(DIM / SBN, ROWS / SBM);    // (8, 64)
    // x = x_in + ctx @ Wo^T -> g_x (fp32)
    gemm_s<<<g1, 256, SMEM3>>>(c16, whi + WOFF_O,
                               x_in, nullptr,
                               x, nullptr, nullptr, ROWS, DIM, DIM);

    // --- MLP block ---
    rmsnorm_kernel<<<ROWS, 256>>>(x, ln2_w, h16);
    dim3 ggu(2 * FFDIM / SBN, ROWS / SBM); // (64, 64)
    gemm_s<<<ggu, 256, SMEM3>>>(h16, whi + WOFF_GU,
                                nullptr, nullptr,
                                nullptr, nullptr, f116, ROWS, 2 * FFDIM, DIM);

    // x_new = x + f1 @ Wdown^T -> fp16 (feeds head GEMM)
    gemm_s<<<g1, 256, SMEM3>>>(f116, whi + WOFF_D,
                               x, nullptr,
                               nullptr, x16, nullptr, ROWS, DIM, FFDIM);

    // --- output head (single-term fp16) ---
    gemm_s<<<g1, 256, SMEM3>>>(x16, whi + WOFF_H,
                               nullptr, b_out,
                               out, nullptr, nullptr, ROWS, DIM, DIM);
}